// round 12
// baseline (speedup 1.0000x reference)
#include <cuda_runtime.h>
#include <cuda_bf16.h>
#include <cstdint>
#include <cstddef>

typedef unsigned int u32;
typedef unsigned long long u64;

#define BATCH 8
#define N_PTS 8192
#define S_MAX 2048

// ---------------- device scratch (allocation-free) ----------------
__device__ int g_idx[BATCH * S_MAX];
__device__ u32 g_featP[BATCH * N_PTS * 256];   // features split-packed (lo<<16|hi)
__device__ u32 g_h1[28672 * 256];              // L1 out packed
__device__ u32 g_procP[16384 * 768];           // fusion input packed (concat, dup)
__device__ u32 g_h2[16384 * 256];              // F1 out packed
__device__ u32 g_w1t[3 * 256 * 256];           // transposed split weights [N,K]
__device__ u32 g_w2t[3 * 256 * 256];
__device__ u32 g_fw1t[256 * 768];
__device__ u32 g_fw2t[256 * 256];

// ---- packed f32x2 helpers (per-lane IEEE rn — bit-identical to scalar) ----
__device__ __forceinline__ u64 pk2(float lo, float hi) {
    u64 r; asm("mov.b64 %0, {%1, %2};" : "=l"(r) : "f"(lo), "f"(hi)); return r;
}
__device__ __forceinline__ void upk2(u64 v, float& lo, float& hi) {
    asm("mov.b64 {%0, %1}, %2;" : "=f"(lo), "=f"(hi) : "l"(v));
}
__device__ __forceinline__ u64 add2(u64 a, u64 b) {
    u64 r; asm("add.rn.f32x2 %0, %1, %2;" : "=l"(r) : "l"(a), "l"(b)); return r;
}
__device__ __forceinline__ u64 mul2(u64 a, u64 b) {
    u64 r; asm("mul.rn.f32x2 %0, %1, %2;" : "=l"(r) : "l"(a), "l"(b)); return r;
}

// ---------------- conversion helper ----------------
__device__ __forceinline__ u32 split_pack_val(float v) {
    __nv_bfloat16 h = __float2bfloat16(v);
    float r = v - __bfloat162float(h);
    __nv_bfloat16 l = __float2bfloat16(r);
    return ((u32)__bfloat16_as_ushort(l) << 16) | (u32)__bfloat16_as_ushort(h);
}

// ---------------------------------------------------------------------------
// fps_all: blocks [0,8): exact spatially-pruned FPS, 1 CTA/batch.
//          blocks [8,2056): features f32 -> split-packed u32.
//          blocks [2056,2136): weight transpose+split conversions.
//
// FPS: Morton-bin 8192 pts into 512 cells (smem counting sort). Warp owns 256
// contiguous sorted points: register bbox + cached (maxbits, origidx, sortpos)
// candidate. Per step: warp prune test (mindist(q,bbox)^2*0.99 >= cached max
// => chunk provably unchanged; 1% margin >> fp rounding). Unpruned warps do
// the exact rn f32x2 update (coords via LDS.64 pairs from sorted smem) and
// rebuild the candidate; ties broken by MIN ORIGINAL INDEX everywhere
// (REDUX min among value-tied lanes / warps) => index sequence bit-identical
// to the unpruned reference regardless of scatter order.
// ---------------------------------------------------------------------------
#define SMEM_FPS 119296
#define FPS_GRID (8 + 2048 + 80)

__global__ void __launch_bounds__(1024, 1)
fps_all(const float* __restrict__ xyz, const float* __restrict__ features,
        const float* __restrict__ w1, const float* __restrict__ w2,
        const float* __restrict__ fw1, const float* __restrict__ fw2,
        int* __restrict__ outIdx, u32* __restrict__ featP,
        u32* __restrict__ w1t, u32* __restrict__ w2t,
        u32* __restrict__ fw1t, u32* __restrict__ fw2t)
{
    const int t = threadIdx.x;

    if (blockIdx.x >= 8) {
        if (blockIdx.x < 2056) {         // features conversion
            const int base = (blockIdx.x - 8) * 8192;
#pragma unroll
            for (int k = 0; k < 8; k++) {
                const int i = base + k * 1024 + t;
                featP[i] = split_pack_val(features[i]);
            }
        } else {                          // weights conversion (concat space)
            const int base = (blockIdx.x - 2056) * 8192;
#pragma unroll
            for (int k = 0; k < 8; k++) {
                const int u = base + k * 1024 + t;
                if (u < 196608) {
                    const int sc = u >> 16, i = u & 65535;
                    const int n = i >> 8, kk = i & 255;
                    w1t[u] = split_pack_val(w1[sc * 65536 + kk * 256 + n]);
                } else if (u < 393216) {
                    const int v = u - 196608;
                    const int sc = v >> 16, i = v & 65535;
                    const int n = i >> 8, kk = i & 255;
                    w2t[v] = split_pack_val(w2[sc * 65536 + kk * 256 + n]);
                } else if (u < 589824) {
                    const int i = u - 393216;
                    const int n = i / 768, kk = i - n * 768;
                    fw1t[i] = split_pack_val(fw1[kk * 256 + n]);
                } else {
                    const int i = u - 589824;
                    const int n = i >> 8, kk = i & 255;
                    fw2t[i] = split_pack_val(fw2[kk * 256 + n]);
                }
            }
        }
        return;
    }

    // ---------------- FPS block ----------------
    extern __shared__ char sm[];
    float* sx = (float*)sm;                         // [8192]
    float* sy = sx + 8192;
    float* sz = sy + 8192;
    unsigned short* sorig = (unsigned short*)(sz + 8192);  // [8192]
    u32* hist  = (u32*)(sorig + 8192);              // [512]
    u32* scan  = hist + 512;                        // [512]
    u32* s_val = scan + 512;                        // [2][32]
    u32* s_key = s_val + 64;                        // [2][32]

    const int b = blockIdx.x;
    const float* p = xyz + (size_t)b * N_PTS * 3;
    const int lane = t & 31, wid = t >> 5;
    const int base = t * 8;

    // ---- bin: histogram ----
    if (t < 512) hist[t] = 0;
    __syncthreads();
    float xr[8], yr[8], zr[8];
    int cells[8];
#pragma unroll
    for (int k = 0; k < 8; k++) {
        const int g = k * 1024 + t;                 // coalesced
        const float x = p[g * 3 + 0], y = p[g * 3 + 1], z = p[g * 3 + 2];
        int bx = (int)(x * 8.0f), by = (int)(y * 8.0f), bz = (int)(z * 8.0f);
        bx = max(0, min(7, bx)); by = max(0, min(7, by)); bz = max(0, min(7, bz));
        // 3-bit morton interleave
        const int sxm = ((bx & 4) << 4) | ((bx & 2) << 2) | (bx & 1);
        const int sym = ((by & 4) << 4) | ((by & 2) << 2) | (by & 1);
        const int szm = ((bz & 4) << 4) | ((bz & 2) << 2) | (bz & 1);
        const int cell = (sxm << 2) | (sym << 1) | szm;
        xr[k] = x; yr[k] = y; zr[k] = z; cells[k] = cell;
        atomicAdd(hist + cell, 1u);
    }
    __syncthreads();
    // ---- inclusive scan over 512 ----
    if (t < 512) scan[t] = hist[t];
    __syncthreads();
    for (int off = 1; off < 512; off <<= 1) {
        u32 v = 0;
        if (t < 512 && t >= off) v = scan[t - off];
        __syncthreads();
        if (t < 512) scan[t] += v;
        __syncthreads();
    }
    if (t < 512) hist[t] = scan[t] - hist[t];       // exclusive base -> cursor
    __syncthreads();
    // ---- scatter ----
#pragma unroll
    for (int k = 0; k < 8; k++) {
        const u32 pos = atomicAdd(hist + cells[k], 1u);
        sx[pos] = xr[k]; sy[pos] = yr[k]; sz[pos] = zr[k];
        sorig[pos] = (unsigned short)(k * 1024 + t);
    }
    __syncthreads();

    // ---- per-thread dist regs; warp bbox ----
    float dist[8];
#pragma unroll
    for (int k = 0; k < 8; k++) dist[k] = 1e10f;

    float mnx = sx[base], mxx = mnx;
    float mny = sy[base], mxy = mny;
    float mnz = sz[base], mxz = mnz;
#pragma unroll
    for (int k = 1; k < 8; k++) {
        mnx = fminf(mnx, sx[base + k]); mxx = fmaxf(mxx, sx[base + k]);
        mny = fminf(mny, sy[base + k]); mxy = fmaxf(mxy, sy[base + k]);
        mnz = fminf(mnz, sz[base + k]); mxz = fmaxf(mxz, sz[base + k]);
    }
#pragma unroll
    for (int off = 16; off > 0; off >>= 1) {
        mnx = fminf(mnx, __shfl_xor_sync(0xFFFFFFFFu, mnx, off));
        mxx = fmaxf(mxx, __shfl_xor_sync(0xFFFFFFFFu, mxx, off));
        mny = fminf(mny, __shfl_xor_sync(0xFFFFFFFFu, mny, off));
        mxy = fmaxf(mxy, __shfl_xor_sync(0xFFFFFFFFu, mxy, off));
        mnz = fminf(mnz, __shfl_xor_sync(0xFFFFFFFFu, mnz, off));
        mxz = fmaxf(mxz, __shfl_xor_sync(0xFFFFFFFFu, mxz, off));
    }

    u32 c_val = 0x7F7FFFFFu;   // FLT_MAX bits: prune impossible until first update
    u32 c_key = 0;

    float qx = p[0], qy = p[1], qz = p[2];
    if (t == 0) outIdx[b * S_MAX + 0] = 0;

    for (int step = 1; step < S_MAX; step++) {
        const int buf = step & 1;
        // ---- warp prune test (warp-uniform) ----
        const float ddx = fmaxf(fmaxf(mnx - qx, qx - mxx), 0.0f);
        const float ddy = fmaxf(fmaxf(mny - qy, qy - mxy), 0.0f);
        const float ddz = fmaxf(fmaxf(mnz - qz, qz - mxz), 0.0f);
        const float md2 = ddx * ddx + ddy * ddy + ddz * ddz;
        const bool prune = (md2 * 0.99f >= __uint_as_float(c_val));

        if (!prune) {
            const u64 nqx = pk2(-qx, -qx);
            const u64 nqy = pk2(-qy, -qy);
            const u64 nqz = pk2(-qz, -qz);
            float bestv = -1.0f;
            int bsp = base;
            u32 besto = 0;
#pragma unroll
            for (int j = 0; j < 4; j++) {
                const int s0 = base + 2 * j;
                const u64 px2 = *(const u64*)(sx + s0);
                const u64 py2 = *(const u64*)(sy + s0);
                const u64 pz2 = *(const u64*)(sz + s0);
                u64 dx = add2(px2, nqx);
                u64 dy = add2(py2, nqy);
                u64 dz = add2(pz2, nqz);
                u64 s  = add2(mul2(dx, dx), mul2(dy, dy));
                u64 d2 = add2(s, mul2(dz, dz));
                float d0, d1;
                upk2(d2, d0, d1);
                const float nd0 = fminf(dist[2 * j + 0], d0);
                const float nd1 = fminf(dist[2 * j + 1], d1);
                dist[2 * j + 0] = nd0;
                dist[2 * j + 1] = nd1;
                if (nd0 > bestv) { bestv = nd0; bsp = s0; besto = sorig[s0]; }
                else if (nd0 == bestv) {
                    const u32 o = sorig[s0];
                    if (o < besto) { bsp = s0; besto = o; }
                }
                if (nd1 > bestv) { bestv = nd1; bsp = s0 + 1; besto = sorig[s0 + 1]; }
                else if (nd1 == bestv) {
                    const u32 o = sorig[s0 + 1];
                    if (o < besto) { bsp = s0 + 1; besto = o; }
                }
            }
            // warp candidate: max value, min orig idx among ties
            const u32 bv = __float_as_uint(bestv);
            const u32 wmax = __reduce_max_sync(0xFFFFFFFFu, bv);
            const u32 mino = __reduce_min_sync(0xFFFFFFFFu,
                                (bv == wmax) ? besto : 0xFFFFFFFFu);
            const u32 selb = __ballot_sync(0xFFFFFFFFu, bv == wmax && besto == mino);
            const int srcl = __ffs(selb) - 1;
            const u32 wsp = (u32)__shfl_sync(0xFFFFFFFFu, bsp, srcl);
            c_val = wmax;
            c_key = (mino << 13) | wsp;
        }
        if (lane == 0) { s_val[buf * 32 + wid] = c_val; s_key[buf * 32 + wid] = c_key; }
        __syncthreads();
        // ---- block stage (all warps redundantly) ----
        const u32 v   = s_val[buf * 32 + lane];
        const u32 key = s_key[buf * 32 + lane];
        const u32 bmax = __reduce_max_sync(0xFFFFFFFFu, v);
        const u32 o = key >> 13;
        const u32 mo2 = __reduce_min_sync(0xFFFFFFFFu,
                            (v == bmax) ? o : 0xFFFFFFFFu);
        const u32 sel2 = __ballot_sync(0xFFFFFFFFu, v == bmax && o == mo2);
        const int ws = __ffs(sel2) - 1;
        const u32 fkey = __shfl_sync(0xFFFFFFFFu, key, ws);
        const u32 sp = fkey & 0x1FFFu;
        if (t == 0) outIdx[b * S_MAX + step] = (int)(fkey >> 13);
        qx = sx[sp]; qy = sy[sp]; qz = sz[sp];
    }
}

// ---------------------------------------------------------------------------
// HMMA (mma.sync m16n8k16 bf16) GEMM — unchanged from R10 (passing).
// ---------------------------------------------------------------------------
#define TCG_SMEM 52608

__device__ __forceinline__ void mma16816(float* c, const u32* a, u32 b0, u32 b1) {
    asm volatile(
        "mma.sync.aligned.m16n8k16.row.col.f32.bf16.bf16.f32 "
        "{%0,%1,%2,%3}, {%4,%5,%6,%7}, {%8,%9}, {%0,%1,%2,%3};"
        : "+f"(c[0]), "+f"(c[1]), "+f"(c[2]), "+f"(c[3])
        : "r"(a[0]), "r"(a[1]), "r"(a[2]), "r"(a[3]), "r"(b0), "r"(b1));
}

template <int AMODE, int EMODE>
__global__ void __launch_bounds__(256, 2)
tc_gemm(const u32* __restrict__ Apk, const u32* __restrict__ Bpk,
        const float* __restrict__ bias, const float* __restrict__ gamma,
        const float* __restrict__ beta, void* __restrict__ Cout,
        int Ktot, const int* __restrict__ idx)
{
    extern __shared__ char smem[];
    u32*    As_hi = (u32*)smem;
    u32*    As_lo = As_hi + 64 * 20;
    u32*    Bs_hi = As_lo + 64 * 20;
    u32*    Bs_lo = Bs_hi + 256 * 20;
    float2* s_ps  = (float2*)(Bs_lo + 256 * 20);
    u32*    s_ro  = (u32*)(s_ps + 128);

    const int tid  = threadIdx.x;
    const int w    = tid >> 5, lane = tid & 31;
    const int g    = lane >> 2, lq = lane & 3;
    const int mrow = (w & 3) * 16;
    const int half = w >> 2;
    const int ncol0 = half * 128;

    int rowblock, sc = 0, hoff = 0, ss = 11;
    if (AMODE == 0 || AMODE == 3) {
        const int blk = blockIdx.x;
        if (blk < 64)       { sc = 0; rowblock = blk * 64;         ss = 9;  hoff = 0; }
        else if (blk < 192) { sc = 1; rowblock = (blk - 64) * 64;  ss = 10; hoff = 4096; }
        else                { sc = 2; rowblock = (blk - 192) * 64; ss = 11; hoff = 12288; }
    } else {
        rowblock = blockIdx.x * 64;
    }
    const u32*   Bp    = Bpk + (size_t)sc * 256 * Ktot;
    const float* biasp = bias + sc * 256;

    if (tid < 64) {
        const int r = rowblock + tid;
        u32 off;
        if (AMODE == 0) {
            const int bb = r >> ss, j = r & ((1 << ss) - 1);
            off = (u32)((bb * 8192 + idx[bb * 2048 + j]) * 256);
        } else if (AMODE == 3) {
            off = (u32)((hoff + r) * 256);
        } else {
            off = (u32)(r * Ktot);
        }
        s_ro[tid] = off;
    }

    float acc[16][4];
#pragma unroll
    for (int t = 0; t < 16; t++)
#pragma unroll
        for (int j = 0; j < 4; j++) acc[t][j] = 0.f;

    const int nch = Ktot >> 5;
    for (int c = 0; c < nch; c++) {
        const int kc = c << 5;
        __syncthreads();
#pragma unroll
        for (int i = 0; i < 2; i++) {
            const int id2 = tid + (i << 8);
            const int row = id2 >> 3, kq = (id2 & 7) << 2;
            const uint4 p = *(const uint4*)(Apk + s_ro[row] + kc + kq);
            const u32 h0 = (p.x & 0xFFFFu) | (p.y << 16);
            const u32 l0 = (p.x >> 16) | (p.y & 0xFFFF0000u);
            const u32 h1 = (p.z & 0xFFFFu) | (p.w << 16);
            const u32 l1 = (p.z >> 16) | (p.w & 0xFFFF0000u);
            const int bo = row * 20 + (kq >> 1);
            *(uint2*)(As_hi + bo) = make_uint2(h0, h1);
            *(uint2*)(As_lo + bo) = make_uint2(l0, l1);
        }
#pragma unroll
        for (int i = 0; i < 8; i++) {
            const int id2 = tid + (i << 8);
            const int row = id2 >> 3, kq = (id2 & 7) << 2;
            const uint4 p = *(const uint4*)(Bp + (size_t)row * Ktot + kc + kq);
            const u32 h0 = (p.x & 0xFFFFu) | (p.y << 16);
            const u32 l0 = (p.x >> 16) | (p.y & 0xFFFF0000u);
            const u32 h1 = (p.z & 0xFFFFu) | (p.w << 16);
            const u32 l1 = (p.z >> 16) | (p.w & 0xFFFF0000u);
            const int bo = row * 20 + (kq >> 1);
            *(uint2*)(Bs_hi + bo) = make_uint2(h0, h1);
            *(uint2*)(Bs_lo + bo) = make_uint2(l0, l1);
        }
        __syncthreads();
#pragma unroll
        for (int ks = 0; ks < 2; ks++) {
            const int kb = ks << 3;
            const int r0 = mrow + g;
            u32 a_h[4], a_l[4];
            a_h[0] = As_hi[r0 * 20 + kb + lq];
            a_h[1] = As_hi[(r0 + 8) * 20 + kb + lq];
            a_h[2] = As_hi[r0 * 20 + kb + 4 + lq];
            a_h[3] = As_hi[(r0 + 8) * 20 + kb + 4 + lq];
            a_l[0] = As_lo[r0 * 20 + kb + lq];
            a_l[1] = As_lo[(r0 + 8) * 20 + kb + lq];
            a_l[2] = As_lo[r0 * 20 + kb + 4 + lq];
            a_l[3] = As_lo[(r0 + 8) * 20 + kb + 4 + lq];
#pragma unroll
            for (int t = 0; t < 16; t++) {
                const int nr = ncol0 + t * 8 + g;
                const u32 bh0 = Bs_hi[nr * 20 + kb + lq];
                const u32 bh1 = Bs_hi[nr * 20 + kb + 4 + lq];
                const u32 bl0 = Bs_lo[nr * 20 + kb + lq];
                const u32 bl1 = Bs_lo[nr * 20 + kb + 4 + lq];
                mma16816(acc[t], a_h, bh0, bh1);
                mma16816(acc[t], a_h, bl0, bl1);
                mma16816(acc[t], a_l, bh0, bh1);
            }
        }
    }

    float2 bv[16];
#pragma unroll
    for (int t = 0; t < 16; t++) {
        bv[t] = *(const float2*)(biasp + ncol0 + t * 8 + lq * 2);
        acc[t][0] += bv[t].x; acc[t][1] += bv[t].y;
        acc[t][2] += bv[t].x; acc[t][3] += bv[t].y;
    }

    const int rAl = mrow + g, rBl = rAl + 8;
    float muA = 0.f, rsA = 1.f, muB = 0.f, rsB = 1.f;
    if (EMODE == 1) {
        float sA = 0.f, qA = 0.f, sB = 0.f, qB = 0.f;
#pragma unroll
        for (int t = 0; t < 16; t++) {
            sA += acc[t][0] + acc[t][1];
            qA += acc[t][0] * acc[t][0] + acc[t][1] * acc[t][1];
            sB += acc[t][2] + acc[t][3];
            qB += acc[t][2] * acc[t][2] + acc[t][3] * acc[t][3];
        }
#pragma unroll
        for (int o = 1; o <= 2; o <<= 1) {
            sA += __shfl_xor_sync(0xFFFFFFFFu, sA, o);
            qA += __shfl_xor_sync(0xFFFFFFFFu, qA, o);
            sB += __shfl_xor_sync(0xFFFFFFFFu, sB, o);
            qB += __shfl_xor_sync(0xFFFFFFFFu, qB, o);
        }
        if (lq == 0) {
            s_ps[half * 64 + rAl] = make_float2(sA, qA);
            s_ps[half * 64 + rBl] = make_float2(sB, qB);
        }
        __syncthreads();
        const float2 pA0 = s_ps[rAl], pA1 = s_ps[64 + rAl];
        const float2 pB0 = s_ps[rBl], pB1 = s_ps[64 + rBl];
        muA = (pA0.x + pA1.x) * (1.0f / 256.0f);
        muB = (pB0.x + pB1.x) * (1.0f / 256.0f);
        const float vA = fmaxf((pA0.y + pA1.y) * (1.0f / 256.0f) - muA * muA, 0.f);
        const float vB = fmaxf((pB0.y + pB1.y) * (1.0f / 256.0f) - muB * muB, 0.f);
        rsA = rsqrtf(vA + 1e-5f);
        rsB = rsqrtf(vB + 1e-5f);
    }

#pragma unroll
    for (int t = 0; t < 16; t++) {
        const int colt0 = ncol0 + t * 8 + lq * 2;
        float o0, o1, o2, o3;
        if (EMODE == 1) {
            const float2 gv = *(const float2*)(gamma + sc * 256 + colt0);
            const float2 ev = *(const float2*)(beta  + sc * 256 + colt0);
            o0 = fmaxf(fmaf((acc[t][0] - muA) * rsA, gv.x, ev.x), 0.f);
            o1 = fmaxf(fmaf((acc[t][1] - muA) * rsA, gv.y, ev.y), 0.f);
            o2 = fmaxf(fmaf((acc[t][2] - muB) * rsB, gv.x, ev.x), 0.f);
            o3 = fmaxf(fmaf((acc[t][3] - muB) * rsB, gv.y, ev.y), 0.f);
        } else {
            o0 = acc[t][0]; o1 = acc[t][1]; o2 = acc[t][2]; o3 = acc[t][3];
        }
        if (EMODE == 1) {
            u32* outU = (u32*)Cout;
            const int gA = hoff + rowblock + rAl;
            const int gB = hoff + rowblock + rBl;
            *(uint2*)(outU + (size_t)gA * 256 + colt0) =
                make_uint2(split_pack_val(o0), split_pack_val(o1));
            *(uint2*)(outU + (size_t)gB * 256 + colt0) =
                make_uint2(split_pack_val(o2), split_pack_val(o3));
        } else if (EMODE == 3) {
            u32* outU = (u32*)Cout;
            const uint2 pA = make_uint2(split_pack_val(o0), split_pack_val(o1));
            const uint2 pB = make_uint2(split_pack_val(o2), split_pack_val(o3));
            const int gA = rowblock + rAl, gB = rowblock + rBl;
            const int bbA = gA >> ss, jA = gA & ((1 << ss) - 1);
            const int bbB = gB >> ss, jB = gB & ((1 << ss) - 1);
            const int reps = 2048 >> ss;
            for (int rep = 0; rep < reps; rep++) {
                *(uint2*)(outU + (size_t)(bbA * 2048 + jA + (rep << ss)) * 768 + sc * 256 + colt0) = pA;
                *(uint2*)(outU + (size_t)(bbB * 2048 + jB + (rep << ss)) * 768 + sc * 256 + colt0) = pB;
            }
        } else {
            float* outF = (float*)Cout;
            const int gA = rowblock + rAl, gB = rowblock + rBl;
            const int bbA = gA >> 11, mA = gA & 2047;
            const int bbB = gB >> 11, mB = gB & 2047;
#pragma unroll
            for (int rep = 0; rep < 4; rep++) {
                *(float2*)(outF + ((size_t)bbA * 8192 + mA + rep * 2048) * 256 + colt0) =
                    make_float2(o0, o1);
                *(float2*)(outF + ((size_t)bbB * 8192 + mB + rep * 2048) * 256 + colt0) =
                    make_float2(o2, o3);
            }
        }
    }
}

// ---------------------------------------------------------------------------
extern "C" void kernel_launch(void* const* d_in, const int* in_sizes, int n_in,
                              void* d_out, int out_size)
{
    const float* features = (const float*)d_in[0];
    const float* xyz      = (const float*)d_in[1];
    const float* w1  = (const float*)d_in[2];
    const float* b1  = (const float*)d_in[3];
    const float* g1  = (const float*)d_in[4];
    const float* be1 = (const float*)d_in[5];
    const float* w2  = (const float*)d_in[6];
    const float* b2  = (const float*)d_in[7];
    const float* fw1 = (const float*)d_in[8];
    const float* fb1 = (const float*)d_in[9];
    const float* fg  = (const float*)d_in[10];
    const float* fbe = (const float*)d_in[11];
    const float* fw2 = (const float*)d_in[12];
    const float* fb2 = (const float*)d_in[13];
    float* out = (float*)d_out;

    int* idxp;   u32 *featP, *h1, *procP, *h2, *w1t, *w2t, *fw1t, *fw2t;
    cudaGetSymbolAddress((void**)&idxp, g_idx);
    cudaGetSymbolAddress((void**)&featP, g_featP);
    cudaGetSymbolAddress((void**)&h1, g_h1);
    cudaGetSymbolAddress((void**)&procP, g_procP);
    cudaGetSymbolAddress((void**)&h2, g_h2);
    cudaGetSymbolAddress((void**)&w1t, g_w1t);
    cudaGetSymbolAddress((void**)&w2t, g_w2t);
    cudaGetSymbolAddress((void**)&fw1t, g_fw1t);
    cudaGetSymbolAddress((void**)&fw2t, g_fw2t);

    cudaFuncSetAttribute(fps_all, cudaFuncAttributeMaxDynamicSharedMemorySize, SMEM_FPS);
    cudaFuncSetAttribute(tc_gemm<0, 1>, cudaFuncAttributeMaxDynamicSharedMemorySize, TCG_SMEM);
    cudaFuncSetAttribute(tc_gemm<3, 3>, cudaFuncAttributeMaxDynamicSharedMemorySize, TCG_SMEM);
    cudaFuncSetAttribute(tc_gemm<1, 1>, cudaFuncAttributeMaxDynamicSharedMemorySize, TCG_SMEM);
    cudaFuncSetAttribute(tc_gemm<1, 2>, cudaFuncAttributeMaxDynamicSharedMemorySize, TCG_SMEM);

    // 0) FPS (exact, spatially pruned) + all conversions in ONE launch.
    fps_all<<<FPS_GRID, 1024, SMEM_FPS>>>(xyz, features, w1, w2, fw1, fw2,
                                          idxp, featP, w1t, w2t, fw1t, fw2t);

    // 1) Per-scale MLPs (448 x 64-row tiles over 28672 rows, scales fused)
    tc_gemm<0, 1><<<448, 256, TCG_SMEM>>>(featP, w1t, b1, g1, be1, h1, 256, idxp);
    tc_gemm<3, 3><<<448, 256, TCG_SMEM>>>(h1, w2t, b2, nullptr, nullptr, procP, 256, nullptr);

    // 2) Fusion MLP on B*2048 distinct rows; final writes 4 tiled copies.
    tc_gemm<1, 1><<<256, 256, TCG_SMEM>>>(procP, fw1t, fb1, fg, fbe, h2, 768, nullptr);
    tc_gemm<1, 2><<<256, 256, TCG_SMEM>>>(h2, fw2t, fb2, nullptr, nullptr, out, 256, nullptr);
}

// round 13
// speedup vs baseline: 1.3908x; 1.3908x over previous
#include <cuda_runtime.h>
#include <cuda_bf16.h>
#include <cstdint>
#include <cstddef>

typedef unsigned int u32;
typedef unsigned long long u64;

#define BATCH 8
#define N_PTS 8192
#define S_MAX 2048

// ---------------- device scratch (allocation-free) ----------------
__device__ int g_idx[BATCH * S_MAX];
__device__ u32 g_featP[BATCH * N_PTS * 256];   // features split-packed (lo<<16|hi)
__device__ u32 g_h1[28672 * 256];              // L1 out packed
__device__ u32 g_procP[16384 * 768];           // fusion input packed (concat, dup)
__device__ u32 g_h2[16384 * 256];              // F1 out packed
__device__ u32 g_w1t[3 * 256 * 256];           // transposed split weights [N,K]
__device__ u32 g_w2t[3 * 256 * 256];
__device__ u32 g_fw1t[256 * 768];
__device__ u32 g_fw2t[256 * 256];

// ---- packed f32x2 helpers (per-lane IEEE rn — bit-identical to scalar) ----
__device__ __forceinline__ u64 pk2(float lo, float hi) {
    u64 r; asm("mov.b64 %0, {%1, %2};" : "=l"(r) : "f"(lo), "f"(hi)); return r;
}
__device__ __forceinline__ void upk2(u64 v, float& lo, float& hi) {
    asm("mov.b64 {%0, %1}, %2;" : "=f"(lo), "=f"(hi) : "l"(v));
}
__device__ __forceinline__ u64 add2(u64 a, u64 b) {
    u64 r; asm("add.rn.f32x2 %0, %1, %2;" : "=l"(r) : "l"(a), "l"(b)); return r;
}
__device__ __forceinline__ u64 mul2(u64 a, u64 b) {
    u64 r; asm("mul.rn.f32x2 %0, %1, %2;" : "=l"(r) : "l"(a), "l"(b)); return r;
}

// ---------------- conversion helper ----------------
__device__ __forceinline__ u32 split_pack_val(float v) {
    __nv_bfloat16 h = __float2bfloat16(v);
    float r = v - __bfloat162float(h);
    __nv_bfloat16 l = __float2bfloat16(r);
    return ((u32)__bfloat16_as_ushort(l) << 16) | (u32)__bfloat16_as_ushort(h);
}

// ---------------------------------------------------------------------------
// fps_all: blocks [0,8): exact spatially-pruned FPS, 1 CTA/batch.
//          blocks [8,2056): features f32 -> split-packed u32.
//          blocks [2056,2136): weight transpose+split conversions.
//
// FPS: Morton-bin into 512 cells (one-time smem counting sort), then load the
// SORTED points back into REGISTERS (f32x2 pairs + packed orig indices) —
// identical inner-loop cost to the R10 register kernel. Warp bbox + cached
// (maxbits, key) candidate enable an exact prune: mindist(q,bbox)^2*0.99 >=
// chunk max dist => no point in the chunk can update (covers all points since
// max >= each dist), and the cached argmax stays valid. 1% margin >> 4-ulp
// rounding. All ties break by MIN ORIGINAL INDEX (lane/warp/block) => index
// sequence bit-identical to the unpruned reference. Smem in steady state is
// only the 3-float winner lookup + 64B/stage reduction slots.
// ---------------------------------------------------------------------------
#define SMEM_FPS 119296
#define FPS_GRID (8 + 2048 + 80)

__global__ void __launch_bounds__(1024, 1)
fps_all(const float* __restrict__ xyz, const float* __restrict__ features,
        const float* __restrict__ w1, const float* __restrict__ w2,
        const float* __restrict__ fw1, const float* __restrict__ fw2,
        int* __restrict__ outIdx, u32* __restrict__ featP,
        u32* __restrict__ w1t, u32* __restrict__ w2t,
        u32* __restrict__ fw1t, u32* __restrict__ fw2t)
{
    const int t = threadIdx.x;

    if (blockIdx.x >= 8) {
        if (blockIdx.x < 2056) {         // features conversion
            const int base = (blockIdx.x - 8) * 8192;
#pragma unroll
            for (int k = 0; k < 8; k++) {
                const int i = base + k * 1024 + t;
                featP[i] = split_pack_val(features[i]);
            }
        } else {                          // weights conversion (concat space)
            const int base = (blockIdx.x - 2056) * 8192;
#pragma unroll
            for (int k = 0; k < 8; k++) {
                const int u = base + k * 1024 + t;
                if (u < 196608) {
                    const int sc = u >> 16, i = u & 65535;
                    const int n = i >> 8, kk = i & 255;
                    w1t[u] = split_pack_val(w1[sc * 65536 + kk * 256 + n]);
                } else if (u < 393216) {
                    const int v = u - 196608;
                    const int sc = v >> 16, i = v & 65535;
                    const int n = i >> 8, kk = i & 255;
                    w2t[v] = split_pack_val(w2[sc * 65536 + kk * 256 + n]);
                } else if (u < 589824) {
                    const int i = u - 393216;
                    const int n = i / 768, kk = i - n * 768;
                    fw1t[i] = split_pack_val(fw1[kk * 256 + n]);
                } else {
                    const int i = u - 589824;
                    const int n = i >> 8, kk = i & 255;
                    fw2t[i] = split_pack_val(fw2[kk * 256 + n]);
                }
            }
        }
        return;
    }

    // ---------------- FPS block ----------------
    extern __shared__ char sm[];
    float* sx = (float*)sm;                         // [8192]
    float* sy = sx + 8192;
    float* sz = sy + 8192;
    unsigned short* sorig = (unsigned short*)(sz + 8192);  // [8192]
    u32* hist  = (u32*)(sorig + 8192);              // [512]
    u32* scan  = hist + 512;                        // [512]
    u32* s_val = scan + 512;                        // [2][32]
    u32* s_key = s_val + 64;                        // [2][32]

    const int b = blockIdx.x;
    const float* p = xyz + (size_t)b * N_PTS * 3;
    const int lane = t & 31, wid = t >> 5;
    const int base = t * 8;

    // ---- bin: histogram ----
    if (t < 512) hist[t] = 0;
    __syncthreads();
    float xr[8], yr[8], zr[8];
    int cells[8];
#pragma unroll
    for (int k = 0; k < 8; k++) {
        const int g = k * 1024 + t;                 // coalesced
        const float x = p[g * 3 + 0], y = p[g * 3 + 1], z = p[g * 3 + 2];
        int bx = (int)(x * 8.0f), by = (int)(y * 8.0f), bz = (int)(z * 8.0f);
        bx = max(0, min(7, bx)); by = max(0, min(7, by)); bz = max(0, min(7, bz));
        const int sxm = ((bx & 4) << 4) | ((bx & 2) << 2) | (bx & 1);
        const int sym = ((by & 4) << 4) | ((by & 2) << 2) | (by & 1);
        const int szm = ((bz & 4) << 4) | ((bz & 2) << 2) | (bz & 1);
        const int cell = (sxm << 2) | (sym << 1) | szm;
        xr[k] = x; yr[k] = y; zr[k] = z; cells[k] = cell;
        atomicAdd(hist + cell, 1u);
    }
    __syncthreads();
    // ---- inclusive scan over 512 ----
    if (t < 512) scan[t] = hist[t];
    __syncthreads();
    for (int off = 1; off < 512; off <<= 1) {
        u32 v = 0;
        if (t < 512 && t >= off) v = scan[t - off];
        __syncthreads();
        if (t < 512) scan[t] += v;
        __syncthreads();
    }
    if (t < 512) hist[t] = scan[t] - hist[t];       // exclusive base -> cursor
    __syncthreads();
    // ---- scatter ----
#pragma unroll
    for (int k = 0; k < 8; k++) {
        const u32 pos = atomicAdd(hist + cells[k], 1u);
        sx[pos] = xr[k]; sy[pos] = yr[k]; sz[pos] = zr[k];
        sorig[pos] = (unsigned short)(k * 1024 + t);
    }
    __syncthreads();

    // ---- load sorted chunk into registers (f32x2 pairs + packed orig) ----
    u64 px2[4], py2[4], pz2[4];
    u32 org[4];
    float dist[8];
#pragma unroll
    for (int j = 0; j < 4; j++) {
        const int s0 = base + 2 * j;
        px2[j] = *(const u64*)(sx + s0);
        py2[j] = *(const u64*)(sy + s0);
        pz2[j] = *(const u64*)(sz + s0);
        org[j] = *(const u32*)(sorig + s0);         // lo16 = pt 2j, hi16 = 2j+1
    }
#pragma unroll
    for (int k = 0; k < 8; k++) dist[k] = 1e10f;

    // ---- warp bbox from registers ----
    float mnx, mxx, mny, mxy, mnz, mxz;
    {
        float a0, a1;
        upk2(px2[0], a0, a1); mnx = fminf(a0, a1); mxx = fmaxf(a0, a1);
        upk2(py2[0], a0, a1); mny = fminf(a0, a1); mxy = fmaxf(a0, a1);
        upk2(pz2[0], a0, a1); mnz = fminf(a0, a1); mxz = fmaxf(a0, a1);
#pragma unroll
        for (int j = 1; j < 4; j++) {
            upk2(px2[j], a0, a1); mnx = fminf(mnx, fminf(a0, a1)); mxx = fmaxf(mxx, fmaxf(a0, a1));
            upk2(py2[j], a0, a1); mny = fminf(mny, fminf(a0, a1)); mxy = fmaxf(mxy, fmaxf(a0, a1));
            upk2(pz2[j], a0, a1); mnz = fminf(mnz, fminf(a0, a1)); mxz = fmaxf(mxz, fmaxf(a0, a1));
        }
#pragma unroll
        for (int off = 16; off > 0; off >>= 1) {
            mnx = fminf(mnx, __shfl_xor_sync(0xFFFFFFFFu, mnx, off));
            mxx = fmaxf(mxx, __shfl_xor_sync(0xFFFFFFFFu, mxx, off));
            mny = fminf(mny, __shfl_xor_sync(0xFFFFFFFFu, mny, off));
            mxy = fmaxf(mxy, __shfl_xor_sync(0xFFFFFFFFu, mxy, off));
            mnz = fminf(mnz, __shfl_xor_sync(0xFFFFFFFFu, mnz, off));
            mxz = fmaxf(mxz, __shfl_xor_sync(0xFFFFFFFFu, mxz, off));
        }
    }

    u32 c_val = 0x7F7FFFFFu;   // FLT_MAX bits: prune impossible until first update
    u32 c_key = 0;

    float qx = p[0], qy = p[1], qz = p[2];
    if (t == 0) outIdx[b * S_MAX + 0] = 0;

    for (int step = 1; step < S_MAX; step++) {
        const int buf = step & 1;
        // ---- warp prune test (warp-uniform; covers all points via chunk max) ----
        const float ddx = fmaxf(fmaxf(mnx - qx, qx - mxx), 0.0f);
        const float ddy = fmaxf(fmaxf(mny - qy, qy - mxy), 0.0f);
        const float ddz = fmaxf(fmaxf(mnz - qz, qz - mxz), 0.0f);
        const float md2 = ddx * ddx + ddy * ddy + ddz * ddz;
        const bool prune = (md2 * 0.99f >= __uint_as_float(c_val));

        if (!prune) {
            const u64 nqx = pk2(-qx, -qx);
            const u64 nqy = pk2(-qy, -qy);
            const u64 nqz = pk2(-qz, -qz);
            float bestv = -1.0f;
            int bsp = base;
            u32 besto = 0xFFFFFFFFu;
#pragma unroll
            for (int j = 0; j < 4; j++) {
                u64 dx = add2(px2[j], nqx);
                u64 dy = add2(py2[j], nqy);
                u64 dz = add2(pz2[j], nqz);
                u64 s  = add2(mul2(dx, dx), mul2(dy, dy));
                u64 d2 = add2(s, mul2(dz, dz));
                float d0, d1;
                upk2(d2, d0, d1);
                const float nd0 = fminf(dist[2 * j + 0], d0);
                const float nd1 = fminf(dist[2 * j + 1], d1);
                dist[2 * j + 0] = nd0;
                dist[2 * j + 1] = nd1;
                const u32 o0 = org[j] & 0xFFFFu;
                const u32 o1 = org[j] >> 16;
                if (nd0 > bestv || (nd0 == bestv && o0 < besto)) {
                    bestv = nd0; bsp = base + 2 * j; besto = o0;
                }
                if (nd1 > bestv || (nd1 == bestv && o1 < besto)) {
                    bestv = nd1; bsp = base + 2 * j + 1; besto = o1;
                }
            }
            // warp candidate: max value, min orig idx among ties
            const u32 bv = __float_as_uint(bestv);
            const u32 wmax = __reduce_max_sync(0xFFFFFFFFu, bv);
            const u32 mino = __reduce_min_sync(0xFFFFFFFFu,
                                (bv == wmax) ? besto : 0xFFFFFFFFu);
            const u32 selb = __ballot_sync(0xFFFFFFFFu, bv == wmax && besto == mino);
            const int srcl = __ffs(selb) - 1;
            const u32 wsp = (u32)__shfl_sync(0xFFFFFFFFu, bsp, srcl);
            c_val = wmax;
            c_key = (mino << 13) | wsp;
        }
        if (lane == 0) { s_val[buf * 32 + wid] = c_val; s_key[buf * 32 + wid] = c_key; }
        __syncthreads();
        // ---- block stage (all warps redundantly) ----
        const u32 v   = s_val[buf * 32 + lane];
        const u32 key = s_key[buf * 32 + lane];
        const u32 bmax = __reduce_max_sync(0xFFFFFFFFu, v);
        const u32 o = key >> 13;
        const u32 mo2 = __reduce_min_sync(0xFFFFFFFFu,
                            (v == bmax) ? o : 0xFFFFFFFFu);
        const u32 sel2 = __ballot_sync(0xFFFFFFFFu, v == bmax && o == mo2);
        const int ws = __ffs(sel2) - 1;
        const u32 fkey = __shfl_sync(0xFFFFFFFFu, key, ws);
        const u32 sp = fkey & 0x1FFFu;
        if (t == 0) outIdx[b * S_MAX + step] = (int)(fkey >> 13);
        qx = sx[sp]; qy = sy[sp]; qz = sz[sp];
    }
}

// ---------------------------------------------------------------------------
// HMMA (mma.sync m16n8k16 bf16) GEMM — unchanged from R10 (passing).
// ---------------------------------------------------------------------------
#define TCG_SMEM 52608

__device__ __forceinline__ void mma16816(float* c, const u32* a, u32 b0, u32 b1) {
    asm volatile(
        "mma.sync.aligned.m16n8k16.row.col.f32.bf16.bf16.f32 "
        "{%0,%1,%2,%3}, {%4,%5,%6,%7}, {%8,%9}, {%0,%1,%2,%3};"
        : "+f"(c[0]), "+f"(c[1]), "+f"(c[2]), "+f"(c[3])
        : "r"(a[0]), "r"(a[1]), "r"(a[2]), "r"(a[3]), "r"(b0), "r"(b1));
}

template <int AMODE, int EMODE>
__global__ void __launch_bounds__(256, 2)
tc_gemm(const u32* __restrict__ Apk, const u32* __restrict__ Bpk,
        const float* __restrict__ bias, const float* __restrict__ gamma,
        const float* __restrict__ beta, void* __restrict__ Cout,
        int Ktot, const int* __restrict__ idx)
{
    extern __shared__ char smem[];
    u32*    As_hi = (u32*)smem;
    u32*    As_lo = As_hi + 64 * 20;
    u32*    Bs_hi = As_lo + 64 * 20;
    u32*    Bs_lo = Bs_hi + 256 * 20;
    float2* s_ps  = (float2*)(Bs_lo + 256 * 20);
    u32*    s_ro  = (u32*)(s_ps + 128);

    const int tid  = threadIdx.x;
    const int w    = tid >> 5, lane = tid & 31;
    const int g    = lane >> 2, lq = lane & 3;
    const int mrow = (w & 3) * 16;
    const int half = w >> 2;
    const int ncol0 = half * 128;

    int rowblock, sc = 0, hoff = 0, ss = 11;
    if (AMODE == 0 || AMODE == 3) {
        const int blk = blockIdx.x;
        if (blk < 64)       { sc = 0; rowblock = blk * 64;         ss = 9;  hoff = 0; }
        else if (blk < 192) { sc = 1; rowblock = (blk - 64) * 64;  ss = 10; hoff = 4096; }
        else                { sc = 2; rowblock = (blk - 192) * 64; ss = 11; hoff = 12288; }
    } else {
        rowblock = blockIdx.x * 64;
    }
    const u32*   Bp    = Bpk + (size_t)sc * 256 * Ktot;
    const float* biasp = bias + sc * 256;

    if (tid < 64) {
        const int r = rowblock + tid;
        u32 off;
        if (AMODE == 0) {
            const int bb = r >> ss, j = r & ((1 << ss) - 1);
            off = (u32)((bb * 8192 + idx[bb * 2048 + j]) * 256);
        } else if (AMODE == 3) {
            off = (u32)((hoff + r) * 256);
        } else {
            off = (u32)(r * Ktot);
        }
        s_ro[tid] = off;
    }

    float acc[16][4];
#pragma unroll
    for (int t = 0; t < 16; t++)
#pragma unroll
        for (int j = 0; j < 4; j++) acc[t][j] = 0.f;

    const int nch = Ktot >> 5;
    for (int c = 0; c < nch; c++) {
        const int kc = c << 5;
        __syncthreads();
#pragma unroll
        for (int i = 0; i < 2; i++) {
            const int id2 = tid + (i << 8);
            const int row = id2 >> 3, kq = (id2 & 7) << 2;
            const uint4 p = *(const uint4*)(Apk + s_ro[row] + kc + kq);
            const u32 h0 = (p.x & 0xFFFFu) | (p.y << 16);
            const u32 l0 = (p.x >> 16) | (p.y & 0xFFFF0000u);
            const u32 h1 = (p.z & 0xFFFFu) | (p.w << 16);
            const u32 l1 = (p.z >> 16) | (p.w & 0xFFFF0000u);
            const int bo = row * 20 + (kq >> 1);
            *(uint2*)(As_hi + bo) = make_uint2(h0, h1);
            *(uint2*)(As_lo + bo) = make_uint2(l0, l1);
        }
#pragma unroll
        for (int i = 0; i < 8; i++) {
            const int id2 = tid + (i << 8);
            const int row = id2 >> 3, kq = (id2 & 7) << 2;
            const uint4 p = *(const uint4*)(Bp + (size_t)row * Ktot + kc + kq);
            const u32 h0 = (p.x & 0xFFFFu) | (p.y << 16);
            const u32 l0 = (p.x >> 16) | (p.y & 0xFFFF0000u);
            const u32 h1 = (p.z & 0xFFFFu) | (p.w << 16);
            const u32 l1 = (p.z >> 16) | (p.w & 0xFFFF0000u);
            const int bo = row * 20 + (kq >> 1);
            *(uint2*)(Bs_hi + bo) = make_uint2(h0, h1);
            *(uint2*)(Bs_lo + bo) = make_uint2(l0, l1);
        }
        __syncthreads();
#pragma unroll
        for (int ks = 0; ks < 2; ks++) {
            const int kb = ks << 3;
            const int r0 = mrow + g;
            u32 a_h[4], a_l[4];
            a_h[0] = As_hi[r0 * 20 + kb + lq];
            a_h[1] = As_hi[(r0 + 8) * 20 + kb + lq];
            a_h[2] = As_hi[r0 * 20 + kb + 4 + lq];
            a_h[3] = As_hi[(r0 + 8) * 20 + kb + 4 + lq];
            a_l[0] = As_lo[r0 * 20 + kb + lq];
            a_l[1] = As_lo[(r0 + 8) * 20 + kb + lq];
            a_l[2] = As_lo[r0 * 20 + kb + 4 + lq];
            a_l[3] = As_lo[(r0 + 8) * 20 + kb + 4 + lq];
#pragma unroll
            for (int t = 0; t < 16; t++) {
                const int nr = ncol0 + t * 8 + g;
                const u32 bh0 = Bs_hi[nr * 20 + kb + lq];
                const u32 bh1 = Bs_hi[nr * 20 + kb + 4 + lq];
                const u32 bl0 = Bs_lo[nr * 20 + kb + lq];
                const u32 bl1 = Bs_lo[nr * 20 + kb + 4 + lq];
                mma16816(acc[t], a_h, bh0, bh1);
                mma16816(acc[t], a_h, bl0, bl1);
                mma16816(acc[t], a_l, bh0, bh1);
            }
        }
    }

    float2 bv[16];
#pragma unroll
    for (int t = 0; t < 16; t++) {
        bv[t] = *(const float2*)(biasp + ncol0 + t * 8 + lq * 2);
        acc[t][0] += bv[t].x; acc[t][1] += bv[t].y;
        acc[t][2] += bv[t].x; acc[t][3] += bv[t].y;
    }

    const int rAl = mrow + g, rBl = rAl + 8;
    float muA = 0.f, rsA = 1.f, muB = 0.f, rsB = 1.f;
    if (EMODE == 1) {
        float sA = 0.f, qA = 0.f, sB = 0.f, qB = 0.f;
#pragma unroll
        for (int t = 0; t < 16; t++) {
            sA += acc[t][0] + acc[t][1];
            qA += acc[t][0] * acc[t][0] + acc[t][1] * acc[t][1];
            sB += acc[t][2] + acc[t][3];
            qB += acc[t][2] * acc[t][2] + acc[t][3] * acc[t][3];
        }
#pragma unroll
        for (int o = 1; o <= 2; o <<= 1) {
            sA += __shfl_xor_sync(0xFFFFFFFFu, sA, o);
            qA += __shfl_xor_sync(0xFFFFFFFFu, qA, o);
            sB += __shfl_xor_sync(0xFFFFFFFFu, sB, o);
            qB += __shfl_xor_sync(0xFFFFFFFFu, qB, o);
        }
        if (lq == 0) {
            s_ps[half * 64 + rAl] = make_float2(sA, qA);
            s_ps[half * 64 + rBl] = make_float2(sB, qB);
        }
        __syncthreads();
        const float2 pA0 = s_ps[rAl], pA1 = s_ps[64 + rAl];
        const float2 pB0 = s_ps[rBl], pB1 = s_ps[64 + rBl];
        muA = (pA0.x + pA1.x) * (1.0f / 256.0f);
        muB = (pB0.x + pB1.x) * (1.0f / 256.0f);
        const float vA = fmaxf((pA0.y + pA1.y) * (1.0f / 256.0f) - muA * muA, 0.f);
        const float vB = fmaxf((pB0.y + pB1.y) * (1.0f / 256.0f) - muB * muB, 0.f);
        rsA = rsqrtf(vA + 1e-5f);
        rsB = rsqrtf(vB + 1e-5f);
    }

#pragma unroll
    for (int t = 0; t < 16; t++) {
        const int colt0 = ncol0 + t * 8 + lq * 2;
        float o0, o1, o2, o3;
        if (EMODE == 1) {
            const float2 gv = *(const float2*)(gamma + sc * 256 + colt0);
            const float2 ev = *(const float2*)(beta  + sc * 256 + colt0);
            o0 = fmaxf(fmaf((acc[t][0] - muA) * rsA, gv.x, ev.x), 0.f);
            o1 = fmaxf(fmaf((acc[t][1] - muA) * rsA, gv.y, ev.y), 0.f);
            o2 = fmaxf(fmaf((acc[t][2] - muB) * rsB, gv.x, ev.x), 0.f);
            o3 = fmaxf(fmaf((acc[t][3] - muB) * rsB, gv.y, ev.y), 0.f);
        } else {
            o0 = acc[t][0]; o1 = acc[t][1]; o2 = acc[t][2]; o3 = acc[t][3];
        }
        if (EMODE == 1) {
            u32* outU = (u32*)Cout;
            const int gA = hoff + rowblock + rAl;
            const int gB = hoff + rowblock + rBl;
            *(uint2*)(outU + (size_t)gA * 256 + colt0) =
                make_uint2(split_pack_val(o0), split_pack_val(o1));
            *(uint2*)(outU + (size_t)gB * 256 + colt0) =
                make_uint2(split_pack_val(o2), split_pack_val(o3));
        } else if (EMODE == 3) {
            u32* outU = (u32*)Cout;
            const uint2 pA = make_uint2(split_pack_val(o0), split_pack_val(o1));
            const uint2 pB = make_uint2(split_pack_val(o2), split_pack_val(o3));
            const int gA = rowblock + rAl, gB = rowblock + rBl;
            const int bbA = gA >> ss, jA = gA & ((1 << ss) - 1);
            const int bbB = gB >> ss, jB = gB & ((1 << ss) - 1);
            const int reps = 2048 >> ss;
            for (int rep = 0; rep < reps; rep++) {
                *(uint2*)(outU + (size_t)(bbA * 2048 + jA + (rep << ss)) * 768 + sc * 256 + colt0) = pA;
                *(uint2*)(outU + (size_t)(bbB * 2048 + jB + (rep << ss)) * 768 + sc * 256 + colt0) = pB;
            }
        } else {
            float* outF = (float*)Cout;
            const int gA = rowblock + rAl, gB = rowblock + rBl;
            const int bbA = gA >> 11, mA = gA & 2047;
            const int bbB = gB >> 11, mB = gB & 2047;
#pragma unroll
            for (int rep = 0; rep < 4; rep++) {
                *(float2*)(outF + ((size_t)bbA * 8192 + mA + rep * 2048) * 256 + colt0) =
                    make_float2(o0, o1);
                *(float2*)(outF + ((size_t)bbB * 8192 + mB + rep * 2048) * 256 + colt0) =
                    make_float2(o2, o3);
            }
        }
    }
}

// ---------------------------------------------------------------------------
extern "C" void kernel_launch(void* const* d_in, const int* in_sizes, int n_in,
                              void* d_out, int out_size)
{
    const float* features = (const float*)d_in[0];
    const float* xyz      = (const float*)d_in[1];
    const float* w1  = (const float*)d_in[2];
    const float* b1  = (const float*)d_in[3];
    const float* g1  = (const float*)d_in[4];
    const float* be1 = (const float*)d_in[5];
    const float* w2  = (const float*)d_in[6];
    const float* b2  = (const float*)d_in[7];
    const float* fw1 = (const float*)d_in[8];
    const float* fb1 = (const float*)d_in[9];
    const float* fg  = (const float*)d_in[10];
    const float* fbe = (const float*)d_in[11];
    const float* fw2 = (const float*)d_in[12];
    const float* fb2 = (const float*)d_in[13];
    float* out = (float*)d_out;

    int* idxp;   u32 *featP, *h1, *procP, *h2, *w1t, *w2t, *fw1t, *fw2t;
    cudaGetSymbolAddress((void**)&idxp, g_idx);
    cudaGetSymbolAddress((void**)&featP, g_featP);
    cudaGetSymbolAddress((void**)&h1, g_h1);
    cudaGetSymbolAddress((void**)&procP, g_procP);
    cudaGetSymbolAddress((void**)&h2, g_h2);
    cudaGetSymbolAddress((void**)&w1t, g_w1t);
    cudaGetSymbolAddress((void**)&w2t, g_w2t);
    cudaGetSymbolAddress((void**)&fw1t, g_fw1t);
    cudaGetSymbolAddress((void**)&fw2t, g_fw2t);

    cudaFuncSetAttribute(fps_all, cudaFuncAttributeMaxDynamicSharedMemorySize, SMEM_FPS);
    cudaFuncSetAttribute(tc_gemm<0, 1>, cudaFuncAttributeMaxDynamicSharedMemorySize, TCG_SMEM);
    cudaFuncSetAttribute(tc_gemm<3, 3>, cudaFuncAttributeMaxDynamicSharedMemorySize, TCG_SMEM);
    cudaFuncSetAttribute(tc_gemm<1, 1>, cudaFuncAttributeMaxDynamicSharedMemorySize, TCG_SMEM);
    cudaFuncSetAttribute(tc_gemm<1, 2>, cudaFuncAttributeMaxDynamicSharedMemorySize, TCG_SMEM);

    // 0) FPS (exact, spatially pruned, register-resident) + all conversions.
    fps_all<<<FPS_GRID, 1024, SMEM_FPS>>>(xyz, features, w1, w2, fw1, fw2,
                                          idxp, featP, w1t, w2t, fw1t, fw2t);

    // 1) Per-scale MLPs (448 x 64-row tiles over 28672 rows, scales fused)
    tc_gemm<0, 1><<<448, 256, TCG_SMEM>>>(featP, w1t, b1, g1, be1, h1, 256, idxp);
    tc_gemm<3, 3><<<448, 256, TCG_SMEM>>>(h1, w2t, b2, nullptr, nullptr, procP, 256, nullptr);

    // 2) Fusion MLP on B*2048 distinct rows; final writes 4 tiled copies.
    tc_gemm<1, 1><<<256, 256, TCG_SMEM>>>(procP, fw1t, fb1, fg, fbe, h2, 768, nullptr);
    tc_gemm<1, 2><<<256, 256, TCG_SMEM>>>(h2, fw2t, fb2, nullptr, nullptr, out, 256, nullptr);
}